// round 16
// baseline (speedup 1.0000x reference)
#include <cuda_runtime.h>
#include <cstdint>

#define IMG_W 4096
#define IMG_H 4096
#define PX    4   // pixels per thread in x; 2 rows per thread => 8 px/thread

// Load 6 consecutive floats (cols x0-1 .. x0+4) of row yy, zero-padded in y.
__device__ __forceinline__ void load_row6(float* n, const float* __restrict__ img,
                                          int yy, int x0, bool lft, bool rgt) {
    if ((unsigned)yy >= (unsigned)IMG_H) {
#pragma unroll
        for (int i = 0; i < 6; i++) n[i] = 0.0f;
        return;
    }
    const float* p = img + (size_t)yy * IMG_W + x0;
    float4 v = __ldg(reinterpret_cast<const float4*>(p));
    n[1] = v.x; n[2] = v.y; n[3] = v.z; n[4] = v.w;
    n[0] = lft ? __ldg(p - 1) : 0.0f;
    n[5] = rgt ? __ldg(p + PX) : 0.0f;
}

// Unchecked variant for rows that are always in range.
__device__ __forceinline__ void load_row6u(float* n, const float* __restrict__ img,
                                           int yy, int x0, bool lft, bool rgt) {
    const float* p = img + (size_t)yy * IMG_W + x0;
    float4 v = __ldg(reinterpret_cast<const float4*>(p));
    n[1] = v.x; n[2] = v.y; n[3] = v.z; n[4] = v.w;
    n[0] = lft ? __ldg(p - 1) : 0.0f;
    n[5] = rgt ? __ldg(p + PX) : 0.0f;
}

// Codes for 4 pixels given V (column triples) and the three rows.
// Decisions bit-identical to all passing rounds: compare tmp +/- di,
// tmp = float_bits(P) & ~7; exact ties -> first index both sides.
// Pipe split (R12, lowest measured ALU work):
//   ALU: 8 fused mask+attach LOP3 + two 4-op VIMNMX3 trees + 2 decode LOP3
//   FMA: 7+1 forced IMADs (opaque 'one') + FADDs + exponent-bias convert
__device__ __forceinline__ void kirsch_px4(const float n0[6], const float n1[6],
                                           const float n2[6], const float V[6],
                                           float code[PX], int one) {
    float pt[PX + 1], pb[PX + 1];
#pragma unroll
    for (int i = 0; i < PX + 1; i++) {
        pt[i] = n0[i] + n0[i + 1];
        pb[i] = n2[i] + n2[i + 1];
    }

#pragma unroll
    for (int j = 1; j <= PX; j++) {
        const float c = n0[j + 1];
        const float d = n1[j - 1];
        const float e = n1[j + 1];
        const float h = n2[j + 1];

        // Kirsch response R_k = 8*P_k - 3*T (T per-pixel const) => order by P_k.
        float P[8];
        P[0] = V[j + 1];        // c+e+h  (N)
        P[1] = pt[j] + e;       // b+c+e  (NW)
        P[2] = pt[j - 1] + c;   // a+b+c  (W)
        P[3] = pt[j - 1] + d;   // a+b+d  (SW)
        P[4] = V[j - 1];        // a+d+f  (S)
        P[5] = pb[j - 1] + d;   // d+f+g  (SE)
        P[6] = pb[j - 1] + h;   // f+g+h  (E)
        P[7] = pb[j] + e;       // e+g+h  (NE)

        // emin[di] = (bits & ~7) | di : one LOP3 (constant lives in a UR).
        // Low bits clear => emin == tmp + di exactly; all P >= 0 so signed
        // int compare == float compare.
        int emin[8];
#pragma unroll
        for (int di = 0; di < 8; di++)
            emin[di] = (int)((__float_as_uint(P[di]) & ~7u) | (unsigned)di);

        // Max side: emax[di] = emin[di]*one - 2*di == tmp - di, IMADs forced
        // onto the FMA pipe ('one' runtime-opaque). Consumed immediately by
        // the max3 tree. Equal tmp strictly decrease with di -> first index.
        int wmax = __vimax3_s32(emin[0], emin[1] * one - 2, emin[2] * one - 4);
        int uA   = __vimax3_s32(emin[3] * one - 6, emin[4] * one - 8,
                                emin[5] * one - 10);
        int uB   = max(emin[6] * one - 12, emin[7] * one - 14);
        wmax = __vimax3_s32(wmax, uA, uB);

        // Min side: pure 3-input tree; ties -> smallest di (first index).
        int wmin = __vimin3_s32(emin[0], emin[1], emin[2]);
        int tA   = __vimin3_s32(emin[3], emin[4], emin[5]);
        int tB   = min(emin[6], emin[7]);
        wmin = __vimin3_s32(wmin, tA, tB);

        // (-8*wmax)&56 == 8*am (tmp_w*8 mult of 64); IMAD on FMA pipe.
        int t1 = wmax * (-8 * one);
        unsigned cb = ((unsigned)t1 & 56u) | 0x4B000000u | ((unsigned)wmin & 7u);
        code[j - 1] = __uint_as_float(cb) - 8388608.0f;  // exponent-bias I2F
    }
}

// 2 output rows per thread; rows y,y+1 need input rows y-1..y+2 (4 loads).
// V-sums share m = r1+r2 between the two rows (-6 FADDs/thread).
__global__ __launch_bounds__(256)
void kirsch_mask_kernel(const float* __restrict__ img, float* __restrict__ out) {
    const int x0 = (blockIdx.x * blockDim.x + threadIdx.x) * PX;
    const int y  = blockIdx.y * 2;
    const bool lft = (x0 > 0);
    const bool rgt = (x0 + PX < IMG_W);

    // Runtime-opaque 1 (blockDim.x == 256) so ptxas cannot strength-reduce
    // the IMADs back onto the ALU pipe (R12: fma% 17.9 -> 26.4).
    const int one = (int)(blockDim.x >> 8);

    float r0[6], r1[6], r2[6], r3[6];
    load_row6 (r0, img, y - 1, x0, lft, rgt);
    load_row6u(r1, img, y,     x0, lft, rgt);  // always in range
    load_row6u(r2, img, y + 1, x0, lft, rgt);  // always in range (y+1<=4095)
    load_row6 (r3, img, y + 2, x0, lft, rgt);

    // Shared middle-row sum for both V's.
    float m[6], VA[6], VB[6];
#pragma unroll
    for (int i = 0; i < 6; i++) m[i]  = r1[i] + r2[i];
#pragma unroll
    for (int i = 0; i < 6; i++) VA[i] = r0[i] + m[i];
#pragma unroll
    for (int i = 0; i < 6; i++) VB[i] = m[i] + r3[i];

    float code[PX];
    kirsch_px4(r0, r1, r2, VA, code, one);
    float4* oA = reinterpret_cast<float4*>(out + (size_t)y * IMG_W + x0);
    *oA = make_float4(code[0], code[1], code[2], code[3]);

    kirsch_px4(r1, r2, r3, VB, code, one);
    float4* oB = reinterpret_cast<float4*>(out + (size_t)(y + 1) * IMG_W + x0);
    *oB = make_float4(code[0], code[1], code[2], code[3]);
}

extern "C" void kernel_launch(void* const* d_in, const int* in_sizes, int n_in,
                              void* d_out, int out_size) {
    const float* img = (const float*)d_in[0];
    for (int i = 0; i < n_in; i++) {
        if (in_sizes[i] == IMG_W * IMG_H) { img = (const float*)d_in[i]; break; }
    }
    float* out = (float*)d_out;

    dim3 block(256, 1, 1);
    dim3 grid(IMG_W / (256 * PX), IMG_H / 2, 1);  // (4, 2048)
    kirsch_mask_kernel<<<grid, block>>>(img, out);
}

// round 17
// speedup vs baseline: 1.1226x; 1.1226x over previous
#include <cuda_runtime.h>
#include <cstdint>

#define IMG_W 4096
#define IMG_H 4096
#define PX    4   // pixels per thread in x; 2 rows per thread => 8 px/thread

// Load 6 consecutive floats (cols x0-1 .. x0+4) of row yy, zero-padded in y.
__device__ __forceinline__ void load_row6(float* n, const float* __restrict__ img,
                                          int yy, int x0, bool lft, bool rgt) {
    if ((unsigned)yy >= (unsigned)IMG_H) {
#pragma unroll
        for (int i = 0; i < 6; i++) n[i] = 0.0f;
        return;
    }
    const float* p = img + (size_t)yy * IMG_W + x0;
    float4 v = __ldg(reinterpret_cast<const float4*>(p));
    n[1] = v.x; n[2] = v.y; n[3] = v.z; n[4] = v.w;
    n[0] = lft ? __ldg(p - 1) : 0.0f;
    n[5] = rgt ? __ldg(p + PX) : 0.0f;
}

// Codes for 4 pixels given rows above/center/below (cols x0-1..x0+4).
// Bit-compare of P-sums with index embedded via fused VIADDMNMX; exact ties
// resolve to the first index on both sides (matches jnp.argmax/argmin).
__device__ __forceinline__ void kirsch_px4(const float n0[6], const float n1[6],
                                           const float n2[6], float code[PX]) {
    float pt[PX + 1], pb[PX + 1], V[PX + 2];
#pragma unroll
    for (int i = 0; i < PX + 1; i++) {
        pt[i] = n0[i] + n0[i + 1];
        pb[i] = n2[i] + n2[i + 1];
    }
#pragma unroll
    for (int i = 0; i < PX + 2; i++) V[i] = n0[i] + n1[i] + n2[i];

#pragma unroll
    for (int j = 1; j <= PX; j++) {
        const float c = n0[j + 1];
        const float d = n1[j - 1];
        const float e = n1[j + 1];
        const float h = n2[j + 1];

        // Kirsch response R_k = 8*P_k - 3*T (T per-pixel const) => order by P_k.
        float P[8];
        P[0] = V[j + 1];        // c+e+h  (N)
        P[1] = pt[j] + e;       // b+c+e  (NW)
        P[2] = pt[j - 1] + c;   // a+b+c  (W)
        P[3] = pt[j - 1] + d;   // a+b+d  (SW)
        P[4] = V[j - 1];        // a+d+f  (S)
        P[5] = pb[j - 1] + d;   // d+f+g  (SE)
        P[6] = pb[j - 1] + h;   // f+g+h  (E)
        P[7] = pb[j] + e;       // e+g+h  (NE)

        // All P >= 0 => signed int compare of float bits == float compare.
        // tmp = bits & ~7: distinct tmp differ by >= 8 > |index addends|.
        int tmp[8];
#pragma unroll
        for (int di = 0; di < 8; di++)
            tmp[di] = (int)(__float_as_uint(P[di]) & ~7u);

        // min(tmp+di): ties pick smallest di (first index).
        int wmin = tmp[0];
        wmin = __viaddmin_s32(tmp[1], 1, wmin);
        wmin = __viaddmin_s32(tmp[2], 2, wmin);
        wmin = __viaddmin_s32(tmp[3], 3, wmin);
        wmin = __viaddmin_s32(tmp[4], 4, wmin);
        wmin = __viaddmin_s32(tmp[5], 5, wmin);
        wmin = __viaddmin_s32(tmp[6], 6, wmin);
        wmin = __viaddmin_s32(tmp[7], 7, wmin);

        // max(tmp-di): ties pick smallest di; recover via (-wmax)&7.
        int wmax = tmp[0];
        wmax = __viaddmax_s32(tmp[1], -1, wmax);
        wmax = __viaddmax_s32(tmp[2], -2, wmax);
        wmax = __viaddmax_s32(tmp[3], -3, wmax);
        wmax = __viaddmax_s32(tmp[4], -4, wmax);
        wmax = __viaddmax_s32(tmp[5], -5, wmax);
        wmax = __viaddmax_s32(tmp[6], -6, wmax);
        wmax = __viaddmax_s32(tmp[7], -7, wmax);

        // code = 8*am + an; int->float via exponent-bias trick (FADD on fma pipe).
        const unsigned am = (0u - (unsigned)wmax) & 7u;
        const unsigned cb = 0x4B000000u | (am << 3) | ((unsigned)wmin & 7u);
        code[j - 1] = __uint_as_float(cb) - 8388608.0f;
    }
}

// 2 output rows per thread: rows y, y+1 need input rows y-1..y+2 (4 loads
// instead of 6) => LDG/px drops 2.25 -> 1.5. Compute row y and store it
// BEFORE row y+1's partials to keep register live set small. Natural register
// allocation (40 regs): every forced cap or restructure over rounds 10-16
// made ptxas emit more instructions and ran slower.
__global__ __launch_bounds__(256)
void kirsch_mask_kernel(const float* __restrict__ img, float* __restrict__ out) {
    const int x0 = (blockIdx.x * blockDim.x + threadIdx.x) * PX;
    const int y  = blockIdx.y * 2;
    const bool lft = (x0 > 0);
    const bool rgt = (x0 + PX < IMG_W);

    float r0[6], r1[6], r2[6], r3[6];
    load_row6(r0, img, y - 1, x0, lft, rgt);
    load_row6(r1, img, y,     x0, lft, rgt);  // always in-range
    load_row6(r2, img, y + 1, x0, lft, rgt);  // always in-range (y+1 <= 4095)
    load_row6(r3, img, y + 2, x0, lft, rgt);

    float code[PX];
    kirsch_px4(r0, r1, r2, code);
    float4* oA = reinterpret_cast<float4*>(out + (size_t)y * IMG_W + x0);
    *oA = make_float4(code[0], code[1], code[2], code[3]);

    kirsch_px4(r1, r2, r3, code);
    float4* oB = reinterpret_cast<float4*>(out + (size_t)(y + 1) * IMG_W + x0);
    *oB = make_float4(code[0], code[1], code[2], code[3]);
}

extern "C" void kernel_launch(void* const* d_in, const int* in_sizes, int n_in,
                              void* d_out, int out_size) {
    const float* img = (const float*)d_in[0];
    for (int i = 0; i < n_in; i++) {
        if (in_sizes[i] == IMG_W * IMG_H) { img = (const float*)d_in[i]; break; }
    }
    float* out = (float*)d_out;

    dim3 block(256, 1, 1);
    dim3 grid(IMG_W / (256 * PX), IMG_H / 2, 1);  // (4, 2048)
    kirsch_mask_kernel<<<grid, block>>>(img, out);
}